// round 10
// baseline (speedup 1.0000x reference)
#include <cuda_runtime.h>

// x:      (4, 64, 128, 128) fp32  -> 256 independent 128x128 images
// weight: (4, 576, 128, 128) fp32 -> 9 taps per channel, tap k strided by H*W
// steps = 8
//
// R9 architecture (best, 62.3us): persistent CTAs (1/SM), 512 thr, V=2
// (warp owns region rows 2g,2g+1 in registers, vertical neighbors via smem
// ping-pong), packed fma.rn.f32x2 stencil, cp.async.bulk staging prefetched
// one tile ahead (10 issuer warps).
// Round 10 deltas:
//  - edge arrays eA/eB (stride-1) for neighbor-row laterals: removes the
//    4-way bank conflicts of the clamped scalar LDS reads
//  - packed prologue: weights processed as f32x2 pairs in their natural
//    layout (abs = 64-bit AND, sums/scale = add/mul.rn.f32x2) -> all 36
//    pk movs eliminated, adds/muls halved

#define H      128
#define W      128
#define IMG    (H * W)
#define STEPS  8
#define TH     16
#define NT     2048
#define SROWS  34
#define RROWS  32

#define OFF_MBAR 0
#define OFF_BUF  1024
#define OFF_EA   (OFF_BUF + 2 * SROWS * W * 4)    // 35840
#define OFF_EB   (OFF_EA + 2 * SROWS * 32 * 4)    // 44544
#define OFF_WS   (OFF_EB + 2 * SROWS * 32 * 4)    // 53248
#define OFF_XS   (OFF_WS + 9 * RROWS * W * 4)     // 200704
#define SMEM_TOTAL (OFF_XS + RROWS * W * 4)       // 217088

typedef unsigned long long u64;
typedef unsigned int u32;

__device__ __forceinline__ u32 s2u(const void* p) {
    u32 a;
    asm("{ .reg .u64 t; cvta.to.shared.u64 t, %1; cvt.u32.u64 %0, t; }"
        : "=r"(a) : "l"(p));
    return a;
}
__device__ __forceinline__ u64 pk(float lo, float hi) {
    u64 r; asm("mov.b64 %0, {%1,%2};" : "=l"(r) : "f"(lo), "f"(hi)); return r;
}
__device__ __forceinline__ void upk(u64 v, float& lo, float& hi) {
    asm("mov.b64 {%0,%1}, %2;" : "=f"(lo), "=f"(hi) : "l"(v));
}
__device__ __forceinline__ void fma2(u64& d, u64 a, u64 b) {
    asm("fma.rn.f32x2 %0, %1, %2, %0;" : "+l"(d) : "l"(a), "l"(b));
}
__device__ __forceinline__ u64 mul2(u64 a, u64 b) {
    u64 d; asm("mul.rn.f32x2 %0, %1, %2;" : "=l"(d) : "l"(a), "l"(b)); return d;
}
__device__ __forceinline__ void add2(u64& d, u64 a) {
    asm("add.rn.f32x2 %0, %0, %1;" : "+l"(d) : "l"(a));
}
__device__ __forceinline__ float shup(float v) { return __shfl_up_sync(0xffffffffu, v, 1); }
__device__ __forceinline__ float shdn(float v) { return __shfl_down_sync(0xffffffffu, v, 1); }

__device__ __forceinline__ void mbar_wait(u32 mbar, u32 parity) {
    asm volatile(
        "{\n\t.reg .pred P;\n\t"
        "W_%=:\n\t"
        "mbarrier.try_wait.parity.shared::cta.b64 P, [%0], %1, 0x989680;\n\t"
        "@P bra.uni D_%=;\n\t"
        "bra.uni W_%=;\n\t"
        "D_%=:\n\t}"
        :: "r"(mbar), "r"(parity) : "memory");
}
__device__ __forceinline__ void bulk_g2s(u32 dst, const void* src, u32 bytes, u32 mbar) {
    asm volatile(
        "cp.async.bulk.shared::cluster.global.mbarrier::complete_tx::bytes "
        "[%0], [%1], %2, [%3];"
        :: "r"(dst), "l"(src), "r"(bytes), "r"(mbar) : "memory");
}

// Distributed prefetch: issuer k (0..8 = weight tap k, 9 = x); mbar count 10.
__device__ __forceinline__ void issue_prefetch_k(int t, int k,
                                                 const float* x, const float* wgt,
                                                 u32 ws, u32 xs, u32 mbar) {
    const int img = t >> 3;
    const int t0  = (t & 7) * TH;
    const int rlo = (t0 - 8 < 0) ? 0 : (t0 - 8);
    const int rhi = (t0 + 24 > H) ? H : (t0 + 24);
    const int nrows = rhi - rlo;
    const int droff = rlo - (t0 - 8);
    const u32 bytes = (u32)nrows * (W * 4);
    asm volatile("mbarrier.arrive.expect_tx.shared.b64 _, [%0], %1;"
                 :: "r"(mbar), "r"(bytes) : "memory");
    if (k < 9) {
        const float* src = wgt + ((size_t)(img * 9 + k) << 14) + rlo * W;
        bulk_g2s(ws + (u32)(k * RROWS + droff) * (W * 4), src, bytes, mbar);
    } else {
        bulk_g2s(xs + (u32)droff * (W * 4), x + ((size_t)img << 14) + rlo * W, bytes, mbar);
    }
}

__global__ __launch_bounds__(512, 1)
void diffusion_persist_kernel(const float* __restrict__ x,
                              const float* __restrict__ wgt,
                              float* __restrict__ out)
{
    extern __shared__ char smem[];
    float (*buf)[SROWS][W] = (float (*)[SROWS][W])(smem + OFF_BUF);
    float (*eA)[SROWS][32] = (float (*)[SROWS][32])(smem + OFF_EA);  // lane's x.w
    float (*eB)[SROWS][32] = (float (*)[SROWS][32])(smem + OFF_EB);  // lane's x.x
    const float* wsp = (const float*)(smem + OFF_WS);
    const float* xsp = (const float*)(smem + OFF_XS);
    const u32 mbar = s2u(smem + OFF_MBAR);
    const u32 ws_a = s2u(smem + OFF_WS);
    const u32 xs_a = s2u(smem + OFF_XS);

    const int tid  = threadIdx.x;
    const int lane = tid & 31;
    const int warp = tid >> 5;          // 0..15; owns region rows 2g, 2g+1
    const int col0 = lane << 2;
    const int g2   = warp * 2;
    // lateral indices into edge arrays (clamped lanes hit zeroed weights)
    const int lL = (lane == 0)  ? 0  : lane - 1;
    const int lR = (lane == 31) ? 31 : lane + 1;
    const bool issuer = (lane == 0 && warp < 10);

    // one-time init: guard rows (region rows -1 and 32 -> zero forever), mbar
    if (tid < 128) {
        int b = tid >> 6, rr = ((tid >> 5) & 1) ? (SROWS - 1) : 0;
        *(float4*)&buf[b][rr][col0] = make_float4(0.f, 0.f, 0.f, 0.f);
        eA[b][rr][lane] = 0.f;
        eB[b][rr][lane] = 0.f;
    }
    if (tid == 0) {
        asm volatile("mbarrier.init.shared.b64 [%0], 10;" :: "r"(mbar) : "memory");
    }
    __syncthreads();

    int t = blockIdx.x;
    const int stride = gridDim.x;
    if (issuer && t < NT) issue_prefetch_k(t, warp, x, wgt, ws_a, xs_a, mbar);
    u32 ph = 0;

    for (; t < NT; t += stride) {
        mbar_wait(mbar, ph); ph ^= 1u;

        const int img = t >> 3;
        const int t0  = (t & 7) * TH;

        // ---- packed prologue: natural-pair weights -> normalized registers
        // Wp[ro][ki][j]: j = {L01,C01,R01,L23,C23,R23}; pairs straight from load
        u64 Wp[2][3][6];
        float4 y0, y1;
#pragma unroll
        for (int ro = 0; ro < 2; ro++) {
            const int rr   = g2 + ro;
            const int grow = t0 - 8 + rr;
            const bool rv  = ((unsigned)grow < (unsigned)H);
            if (rv) {
                u64 ab01[9], ab23[9];
                u64 s01 = 0ull, s23 = 0ull;
#pragma unroll
                for (int k = 0; k < 9; k++) {
                    ulonglong2 tv = *(const ulonglong2*)&wsp[(k * RROWS + rr) * W + col0];
                    ab01[k] = tv.x & 0x7fffffff7fffffffULL;
                    ab23[k] = tv.y & 0x7fffffff7fffffffULL;
                    if (k == 0) { s01 = ab01[0]; s23 = ab23[0]; }
                    else        { add2(s01, ab01[k]); add2(s23, ab23[k]); }
                }
                float s0, s1, s2, s3;
                upk(s01, s0, s1); upk(s23, s2, s3);
                const u64 i01 = pk(__fdividef(1.f, s0), __fdividef(1.f, s1));
                const u64 i23 = pk(__fdividef(1.f, s2), __fdividef(1.f, s3));
#pragma unroll
                for (int ki = 0; ki < 3; ki++) {
                    Wp[ro][ki][0] = mul2(ab01[ki * 3 + 0], i01);
                    Wp[ro][ki][1] = mul2(ab01[ki * 3 + 1], i01);
                    Wp[ro][ki][2] = mul2(ab01[ki * 3 + 2], i01);
                    Wp[ro][ki][3] = mul2(ab23[ki * 3 + 0], i23);
                    Wp[ro][ki][4] = mul2(ab23[ki * 3 + 1], i23);
                    Wp[ro][ki][5] = mul2(ab23[ki * 3 + 2], i23);
                }
                // fold image left/right zero padding into edge-lane weights
                if (lane == 0) {
#pragma unroll
                    for (int ki = 0; ki < 3; ki++)
                        Wp[ro][ki][0] &= 0xffffffff00000000ULL;  // zero w(x0,L)
                }
                if (lane == 31) {
#pragma unroll
                    for (int ki = 0; ki < 3; ki++)
                        Wp[ro][ki][5] &= 0x00000000ffffffffULL;  // zero w(x3,R)
                }
            } else {
#pragma unroll
                for (int ki = 0; ki < 3; ki++)
#pragma unroll
                    for (int j = 0; j < 6; j++) Wp[ro][ki][j] = 0ull;
            }
            float4 xv = make_float4(0.f, 0.f, 0.f, 0.f);
            if (rv) xv = *(const float4*)&xsp[rr * W + col0];
            if (ro == 0) y0 = xv; else y1 = xv;
            *(float4*)&buf[0][rr + 1][col0] = xv;
            eA[0][rr + 1][lane] = xv.w;
            eB[0][rr + 1][lane] = xv.x;
        }

        // hoisted own-row operands for step 0 (register-only; pre-barrier)
        u64 p00, p01, p02, p03, p04, p10, p11, p12, p13, p14;
        {
            const float xl0 = shup(y0.w), xr0 = shdn(y0.x);
            const float xl1 = shup(y1.w), xr1 = shdn(y1.x);
            p00 = pk(xl0, y0.x); p01 = pk(y0.x, y0.y); p02 = pk(y0.y, y0.z);
            p03 = pk(y0.z, y0.w); p04 = pk(y0.w, xr0);
            p10 = pk(xl1, y1.x); p11 = pk(y1.x, y1.y); p12 = pk(y1.y, y1.z);
            p13 = pk(y1.z, y1.w); p14 = pk(y1.w, xr1);
        }
        __syncthreads();   // staging consumed + buf[0]/edges published

        // prefetch next tile (distributed; overlaps the 8-step loop)
        if (issuer && t + stride < NT)
            issue_prefetch_k(t + stride, warp, x, wgt, ws_a, xs_a, mbar);

        // ---- 8 fused steps
#pragma unroll
        for (int s = 0; s < STEPS; s++) {
            const int cb = s & 1;
            // neighbor rows: vector LDS + conflict-free edge-array laterals
            float4 va = *(const float4*)&buf[cb][g2][col0];      // row 2g-1
            const float vaL = eA[cb][g2][lL], vaR = eB[cb][g2][lR];
            float4 vb = *(const float4*)&buf[cb][g2 + 3][col0];  // row 2g+2
            const float vbL = eA[cb][g2 + 3][lL], vbR = eB[cb][g2 + 3][lR];

            const u64 pA0 = pk(vaL, va.x), pA1 = pk(va.x, va.y), pA2 = pk(va.y, va.z);
            const u64 pA3 = pk(va.z, va.w), pA4 = pk(va.w, vaR);
            const u64 pB0 = pk(vbL, vb.x), pB1 = pk(vb.x, vb.y), pB2 = pk(vb.y, vb.z);
            const u64 pB3 = pk(vb.z, vb.w), pB4 = pk(vb.w, vbR);

            // chains start on own-row operands (ready at loop top)
            u64 n001 = mul2(Wp[0][1][0], p00), n023 = mul2(Wp[0][1][3], p02);
            u64 n101 = mul2(Wp[1][0][0], p00), n123 = mul2(Wp[1][0][3], p02);
            fma2(n001, Wp[0][1][1], p01); fma2(n023, Wp[0][1][4], p03);
            fma2(n101, Wp[1][0][1], p01); fma2(n123, Wp[1][0][4], p03);
            fma2(n001, Wp[0][1][2], p02); fma2(n023, Wp[0][1][5], p04);
            fma2(n101, Wp[1][0][2], p02); fma2(n123, Wp[1][0][5], p04);

            fma2(n001, Wp[0][2][0], p10); fma2(n023, Wp[0][2][3], p12);
            fma2(n101, Wp[1][1][0], p10); fma2(n123, Wp[1][1][3], p12);
            fma2(n001, Wp[0][2][1], p11); fma2(n023, Wp[0][2][4], p13);
            fma2(n101, Wp[1][1][1], p11); fma2(n123, Wp[1][1][4], p13);
            fma2(n001, Wp[0][2][2], p12); fma2(n023, Wp[0][2][5], p14);
            fma2(n101, Wp[1][1][2], p12); fma2(n123, Wp[1][1][5], p14);

            fma2(n001, Wp[0][0][0], pA0); fma2(n023, Wp[0][0][3], pA2);
            fma2(n101, Wp[1][2][0], pB0); fma2(n123, Wp[1][2][3], pB2);
            fma2(n001, Wp[0][0][1], pA1); fma2(n023, Wp[0][0][4], pA3);
            fma2(n101, Wp[1][2][1], pB1); fma2(n123, Wp[1][2][4], pB3);
            fma2(n001, Wp[0][0][2], pA2); fma2(n023, Wp[0][0][5], pA4);
            fma2(n101, Wp[1][2][2], pB2); fma2(n123, Wp[1][2][5], pB4);

            upk(n001, y0.x, y0.y); upk(n023, y0.z, y0.w);
            upk(n101, y1.x, y1.y); upk(n123, y1.z, y1.w);

            if (s < STEPS - 1) {
                // hoist next step's own-row operands BEFORE the barrier
                const float xl0 = shup(y0.w), xr0 = shdn(y0.x);
                const float xl1 = shup(y1.w), xr1 = shdn(y1.x);
                p00 = pk(xl0, y0.x); p01 = pk(y0.x, y0.y); p02 = pk(y0.y, y0.z);
                p03 = pk(y0.z, y0.w); p04 = pk(y0.w, xr0);
                p10 = pk(xl1, y1.x); p11 = pk(y1.x, y1.y); p12 = pk(y1.y, y1.z);
                p13 = pk(y1.z, y1.w); p14 = pk(y1.w, xr1);

                const int nb = cb ^ 1;
                *(float4*)&buf[nb][g2 + 1][col0] = y0;
                *(float4*)&buf[nb][g2 + 2][col0] = y1;
                eA[nb][g2 + 1][lane] = y0.w;  eB[nb][g2 + 1][lane] = y0.x;
                eA[nb][g2 + 2][lane] = y1.w;  eB[nb][g2 + 2][lane] = y1.x;
                __syncthreads();
            }
        }

        // ---- output: warps 4..11 hold the 16 exact rows (region rows 8..23)
        if ((unsigned)(warp - 4) < 8u) {
            float* ob = out + (size_t)img * IMG + (t0 + g2 - 8) * W + col0;
            *(float4*)ob       = y0;
            *(float4*)(ob + W) = y1;
        }
        // Next-tile prologue writes buf[0]/edges[0] only; last reads of those
        // were step 6, fenced by the step-6 __syncthreads. Staging reuse is
        // fenced by mbar + post-prologue __syncthreads.
    }
}

extern "C" void kernel_launch(void* const* d_in, const int* in_sizes, int n_in,
                              void* d_out, int out_size)
{
    const float* x   = (const float*)d_in[0];
    const float* wgt = (const float*)d_in[1];
    float* out       = (float*)d_out;

    int sms = 148;
    cudaDeviceGetAttribute(&sms, cudaDevAttrMultiProcessorCount, 0);
    if (sms < 1) sms = 148;
    if (sms > NT) sms = NT;

    cudaFuncSetAttribute(diffusion_persist_kernel,
                         cudaFuncAttributeMaxDynamicSharedMemorySize, SMEM_TOTAL);
    diffusion_persist_kernel<<<sms, 512, SMEM_TOTAL>>>(x, wgt, out);
}